// round 1
// baseline (speedup 1.0000x reference)
#include <cuda_runtime.h>
#include <cuda_bf16.h>
#include <math_constants.h>

// Problem constants (fixed shapes per reference: B=4, T=4096, D=512, K=8192)
#define DDIM    512
#define N_ROWS  16384
#define K_CODES 8192
#define BM      64
#define BK      64
#define DC      16

// Scratch (allocation-free): per-code bias and per-row argmax index
__device__ float g_bias[K_CODES];   // -0.5 * ||e_k||^2
__device__ int   g_ind[N_ROWS];

// ---------------------------------------------------------------------------
// Kernel 1: per-code bias = -0.5 * sum(e^2).  One warp per code.
// ---------------------------------------------------------------------------
__global__ void esq_kernel(const float* __restrict__ embed) {
    int warp = (blockIdx.x * blockDim.x + threadIdx.x) >> 5;
    int lane = threadIdx.x & 31;
    if (warp >= K_CODES) return;
    const float4* row = reinterpret_cast<const float4*>(embed + (size_t)warp * DDIM);
    float s = 0.f;
#pragma unroll
    for (int i = 0; i < 4; i++) {          // 512 floats = 128 float4 = 32 lanes * 4
        float4 v = row[lane + 32 * i];
        s += v.x * v.x + v.y * v.y + v.z * v.z + v.w * v.w;
    }
#pragma unroll
    for (int off = 16; off; off >>= 1) s += __shfl_xor_sync(0xFFFFFFFFu, s, off);
    if (lane == 0) g_bias[warp] = -0.5f * s;
}

// ---------------------------------------------------------------------------
// Kernel 2: fused score-GEMM + running argmax.
// Block: 64 x-rows vs all 8192 codes. 256 threads as 16x16; each thread owns a
// 4x4 register tile of the 64x64 score block. score = x.e - 0.5||e||^2.
// ---------------------------------------------------------------------------
__global__ __launch_bounds__(256, 2) void vq_kernel(const float* __restrict__ x,
                                                    const float* __restrict__ embed) {
    __shared__ __align__(16) float xs[DC][BM];   // xs[d][m]
    __shared__ __align__(16) float es[DC][BK];   // es[d][k]

    const int tid = threadIdx.x;
    const int tx  = tid & 15;        // column group (codes)
    const int ty  = tid >> 4;        // row group (x rows)
    const int row0 = blockIdx.x * BM;

    // loader mapping: 256 threads cover 64 rows x 4 float4 per D-chunk
    const int lm = tid >> 2;         // 0..63 : row within tile
    const int lc = tid & 3;          // 0..3  : float4 within 16-float chunk

    float best[4];
    int   bidx[4];
#pragma unroll
    for (int i = 0; i < 4; i++) { best[i] = -CUDART_INF_F; bidx[i] = 0; }

    for (int k0 = 0; k0 < K_CODES; k0 += BK) {
        // init accumulators with code bias (-0.5||e||^2)
        float acc[4][4];
        {
            const float4 bv = *reinterpret_cast<const float4*>(&g_bias[k0 + tx * 4]);
            float bias[4] = {bv.x, bv.y, bv.z, bv.w};
#pragma unroll
            for (int i = 0; i < 4; i++)
#pragma unroll
                for (int j = 0; j < 4; j++) acc[i][j] = bias[j];
        }

        const float* xg = x     + (size_t)(row0 + lm) * DDIM + lc * 4;
        const float* eg = embed + (size_t)(k0   + lm) * DDIM + lc * 4;

        for (int d0 = 0; d0 < DDIM; d0 += DC) {
            __syncthreads();
            float4 xv = *reinterpret_cast<const float4*>(xg + d0);
            float4 ev = *reinterpret_cast<const float4*>(eg + d0);
            xs[lc * 4 + 0][lm] = xv.x;
            xs[lc * 4 + 1][lm] = xv.y;
            xs[lc * 4 + 2][lm] = xv.z;
            xs[lc * 4 + 3][lm] = xv.w;
            es[lc * 4 + 0][lm] = ev.x;
            es[lc * 4 + 1][lm] = ev.y;
            es[lc * 4 + 2][lm] = ev.z;
            es[lc * 4 + 3][lm] = ev.w;
            __syncthreads();

#pragma unroll
            for (int d = 0; d < DC; d++) {
                float4 a = *reinterpret_cast<const float4*>(&xs[d][ty * 4]);
                float4 b = *reinterpret_cast<const float4*>(&es[d][tx * 4]);
                acc[0][0] += a.x * b.x; acc[0][1] += a.x * b.y; acc[0][2] += a.x * b.z; acc[0][3] += a.x * b.w;
                acc[1][0] += a.y * b.x; acc[1][1] += a.y * b.y; acc[1][2] += a.y * b.z; acc[1][3] += a.y * b.w;
                acc[2][0] += a.z * b.x; acc[2][1] += a.z * b.y; acc[2][2] += a.z * b.z; acc[2][3] += a.z * b.w;
                acc[3][0] += a.w * b.x; acc[3][1] += a.w * b.y; acc[3][2] += a.w * b.z; acc[3][3] += a.w * b.w;
            }
        }

        // per-row argmax over this 64-code tile (ascending index, strict > =>
        // first-max-index semantics, matching jnp.argmax)
#pragma unroll
        for (int i = 0; i < 4; i++) {
            float v = acc[i][0];
            int   ji = 0;
#pragma unroll
            for (int j = 1; j < 4; j++) {
                if (acc[i][j] > v) { v = acc[i][j]; ji = j; }
            }
            int idx = k0 + tx * 4 + ji;
            // butterfly reduce across the 16 lanes sharing this row group
#pragma unroll
            for (int off = 8; off; off >>= 1) {
                float ov = __shfl_xor_sync(0xFFFFFFFFu, v, off, 16);
                int   oi = __shfl_xor_sync(0xFFFFFFFFu, idx, off, 16);
                if (ov > v || (ov == v && oi < idx)) { v = ov; idx = oi; }
            }
            if (v > best[i]) { best[i] = v; bidx[i] = idx; }
        }
    }

    if (tx == 0) {
#pragma unroll
        for (int i = 0; i < 4; i++) g_ind[row0 + ty * 4 + i] = bidx[i];
    }
}

// ---------------------------------------------------------------------------
// Kernel 3: gather selected codebook rows -> out[0 : N*D); indices (as float)
// -> out[N*D : N*D + N) when the output buffer carries both tuple members.
// ---------------------------------------------------------------------------
__global__ void gather_kernel(const float* __restrict__ embed,
                              float* __restrict__ out, int write_ind) {
    int n = blockIdx.x;
    int idx = g_ind[n];
    const float4* src = reinterpret_cast<const float4*>(embed + (size_t)idx * DDIM);
    float4*       dst = reinterpret_cast<float4*>(out + (size_t)n * DDIM);
    for (int i = threadIdx.x; i < DDIM / 4; i += blockDim.x) dst[i] = src[i];
    if (write_ind && threadIdx.x == 0) out[(size_t)N_ROWS * DDIM + n] = (float)idx;
}

// ---------------------------------------------------------------------------
extern "C" void kernel_launch(void* const* d_in, const int* in_sizes, int n_in,
                              void* d_out, int out_size) {
    const float* x     = (const float*)d_in[0];   // [B,T,D] float32
    const float* embed = (const float*)d_in[1];   // [K,D]   float32
    float* out = (float*)d_out;

    (void)in_sizes; (void)n_in;
    int write_ind = (out_size >= N_ROWS * DDIM + N_ROWS) ? 1 : 0;

    esq_kernel<<<K_CODES / 8, 256>>>(embed);                 // 8 warps/block
    vq_kernel<<<N_ROWS / BM, 256>>>(x, embed);
    gather_kernel<<<N_ROWS, 128>>>(embed, out, write_ind);
}

// round 3
// speedup vs baseline: 6.7318x; 6.7318x over previous
#include <cuda_runtime.h>
#include <cuda_bf16.h>
#include <math_constants.h>
#include <cstdint>

#define DDIM    512
#define N_ROWS  16384
#define K_CODES 8192

// ---- pass-1 GEMM tiling ----
#define BM      128           // x rows per CTA
#define BN      256           // codes per CTA
#define BKH     32            // K-chunk in halves (bf16) = 64B/row
#define NCHUNK  (DDIM / BKH)  // 16
#define ROWSTR_H 40           // smem row stride in halves (80B) -> conflict-free
#define ROWSTR_B 80
#define STAGE_B ((BM + BN) * ROWSTR_B)   // 30720
#define NSTAGE  3
#define SMEM_GEMM (NSTAGE * STAGE_B)     // 92160

// ---- device scratch (allocation-free) ----
__device__ __nv_bfloat16 g_xb[(size_t)N_ROWS * DDIM];
__device__ __nv_bfloat16 g_eb[(size_t)K_CODES * DDIM];
__device__ __align__(16) float g_bias[K_CODES];     // -0.5*||e||^2
__device__ float g_xnorm[N_ROWS];                   // ||x_row||
__device__ int   g_emax2;                           // max ||e||^2 (float bits)
__device__ float g_scores[(size_t)N_ROWS * K_CODES];  // 512 MB
__device__ int   g_ind[N_ROWS];

// ---------------------------------------------------------------------------
__device__ __forceinline__ uint32_t smem_u32(const void* p) {
    uint32_t a;
    asm("{ .reg .u64 t; cvta.to.shared.u64 t, %1; cvt.u32.u64 %0, t; }" : "=r"(a) : "l"(p));
    return a;
}
__device__ __forceinline__ void cp16(uint32_t dst, const void* src) {
    asm volatile("cp.async.cg.shared.global [%0], [%1], 16;" :: "r"(dst), "l"(src) : "memory");
}
#define CP_COMMIT() asm volatile("cp.async.commit_group;" ::: "memory")
#define CP_WAIT2()  asm volatile("cp.async.wait_group 2;" ::: "memory")

__device__ __forceinline__ void mma_bf16(float* d, const uint32_t* a, const uint32_t* b) {
    asm volatile(
        "mma.sync.aligned.m16n8k16.row.col.f32.bf16.bf16.f32 "
        "{%0,%1,%2,%3}, {%4,%5,%6,%7}, {%8,%9}, {%0,%1,%2,%3};"
        : "+f"(d[0]), "+f"(d[1]), "+f"(d[2]), "+f"(d[3])
        : "r"(a[0]), "r"(a[1]), "r"(a[2]), "r"(a[3]), "r"(b[0]), "r"(b[1]));
}

// ---------------------------------------------------------------------------
// Convert x -> bf16, per-row ||x||.  One warp per row.
// ---------------------------------------------------------------------------
__global__ void conv_x_kernel(const float* __restrict__ x) {
    int row = (blockIdx.x * blockDim.x + threadIdx.x) >> 5;
    int lane = threadIdx.x & 31;
    if (row >= N_ROWS) return;
    const float4* src = reinterpret_cast<const float4*>(x + (size_t)row * DDIM);
    uint4* dst = reinterpret_cast<uint4*>(g_xb + (size_t)row * DDIM);
    float s = 0.f;
#pragma unroll
    for (int j = 0; j < 2; j++) {          // lane covers 16 floats -> 32B bf16
        __nv_bfloat162 h[4];
        float4 v0 = src[lane * 4 + j * 2];
        float4 v1 = src[lane * 4 + j * 2 + 1];
        s += v0.x*v0.x + v0.y*v0.y + v0.z*v0.z + v0.w*v0.w;
        s += v1.x*v1.x + v1.y*v1.y + v1.z*v1.z + v1.w*v1.w;
        h[0] = __nv_bfloat162(__float2bfloat16_rn(v0.x), __float2bfloat16_rn(v0.y));
        h[1] = __nv_bfloat162(__float2bfloat16_rn(v0.z), __float2bfloat16_rn(v0.w));
        h[2] = __nv_bfloat162(__float2bfloat16_rn(v1.x), __float2bfloat16_rn(v1.y));
        h[3] = __nv_bfloat162(__float2bfloat16_rn(v1.z), __float2bfloat16_rn(v1.w));
        dst[lane * 2 + j] = *reinterpret_cast<uint4*>(h);
    }
#pragma unroll
    for (int off = 16; off; off >>= 1) s += __shfl_xor_sync(0xFFFFFFFFu, s, off);
    if (lane == 0) g_xnorm[row] = sqrtf(s);
}

// Convert embed -> bf16, bias, max ||e||^2.
__global__ void conv_e_kernel(const float* __restrict__ e) {
    int row = (blockIdx.x * blockDim.x + threadIdx.x) >> 5;
    int lane = threadIdx.x & 31;
    if (row >= K_CODES) return;
    const float4* src = reinterpret_cast<const float4*>(e + (size_t)row * DDIM);
    uint4* dst = reinterpret_cast<uint4*>(g_eb + (size_t)row * DDIM);
    float s = 0.f;
#pragma unroll
    for (int j = 0; j < 2; j++) {
        __nv_bfloat162 h[4];
        float4 v0 = src[lane * 4 + j * 2];
        float4 v1 = src[lane * 4 + j * 2 + 1];
        s += v0.x*v0.x + v0.y*v0.y + v0.z*v0.z + v0.w*v0.w;
        s += v1.x*v1.x + v1.y*v1.y + v1.z*v1.z + v1.w*v1.w;
        h[0] = __nv_bfloat162(__float2bfloat16_rn(v0.x), __float2bfloat16_rn(v0.y));
        h[1] = __nv_bfloat162(__float2bfloat16_rn(v0.z), __float2bfloat16_rn(v0.w));
        h[2] = __nv_bfloat162(__float2bfloat16_rn(v1.x), __float2bfloat16_rn(v1.y));
        h[3] = __nv_bfloat162(__float2bfloat16_rn(v1.z), __float2bfloat16_rn(v1.w));
        dst[lane * 2 + j] = *reinterpret_cast<uint4*>(h);
    }
#pragma unroll
    for (int off = 16; off; off >>= 1) s += __shfl_xor_sync(0xFFFFFFFFu, s, off);
    if (lane == 0) {
        g_bias[row] = -0.5f * s;
        atomicMax(&g_emax2, __float_as_int(s));   // positive floats: int order ok
    }
}

// ---------------------------------------------------------------------------
// Pass 1: approx scores via bf16 mma.sync.  256 thr, 8 warps (2m x 4n),
// warp tile 64x64, CTA tile 128x256, 3-stage cp.async pipeline.
// ---------------------------------------------------------------------------
extern __shared__ char smem_g[];

__device__ __forceinline__ void gemm_issue(uint32_t smb, int stage, int row0, int col0,
                                           int chunk, int tid) {
    const int d0 = chunk * BKH;
    const uint32_t st = smb + stage * STAGE_B;
#pragma unroll
    for (int it = 0; it < 6; it++) {               // 1536 cp16 / 256 threads
        int i = tid + it * 256;
        int r = i >> 2, c = i & 3;
        if (r < BM) {
            const __nv_bfloat16* src = g_xb + (size_t)(row0 + r) * DDIM + d0 + c * 8;
            cp16(st + r * ROWSTR_B + c * 16, src);
        } else {
            int r2 = r - BM;
            const __nv_bfloat16* src = g_eb + (size_t)(col0 + r2) * DDIM + d0 + c * 8;
            cp16(st + BM * ROWSTR_B + r2 * ROWSTR_B + c * 16, src);
        }
    }
}

__global__ __launch_bounds__(256, 1) void gemm_kernel() {
    const int tid = threadIdx.x;
    const int lane = tid & 31;
    const int wid = tid >> 5;
    const int wm = wid >> 2;            // 0..1
    const int wn = wid & 3;             // 0..3
    const int g = lane >> 2;            // 0..7
    const int q = lane & 3;             // 0..3
    const int col0 = blockIdx.x * BN;
    const int row0 = blockIdx.y * BM;
    const uint32_t smb = smem_u32(smem_g);

    float acc[4][8][4];
#pragma unroll
    for (int mt = 0; mt < 4; mt++)
#pragma unroll
        for (int nt = 0; nt < 8; nt++)
#pragma unroll
            for (int c = 0; c < 4; c++) acc[mt][nt][c] = 0.f;

    gemm_issue(smb, 0, row0, col0, 0, tid); CP_COMMIT();
    gemm_issue(smb, 1, row0, col0, 1, tid); CP_COMMIT();

    for (int ch = 0; ch < NCHUNK; ch++) {
        if (ch + 2 < NCHUNK) gemm_issue(smb, (ch + 2) % NSTAGE, row0, col0, ch + 2, tid);
        CP_COMMIT();
        CP_WAIT2();
        __syncthreads();

        const uint32_t* sa = reinterpret_cast<const uint32_t*>(smem_g + (ch % NSTAGE) * STAGE_B);
        const uint32_t* sb = sa + BM * (ROWSTR_B / 4);

#pragma unroll
        for (int s = 0; s < 2; s++) {           // two k16 steps per chunk
            const int s8 = s * 8;
            uint32_t a[4][4], b[8][2];
#pragma unroll
            for (int mt = 0; mt < 4; mt++) {
                int r = wm * 64 + mt * 16 + g;
                a[mt][0] = sa[r * 20 + q + s8];
                a[mt][1] = sa[(r + 8) * 20 + q + s8];
                a[mt][2] = sa[r * 20 + q + 4 + s8];
                a[mt][3] = sa[(r + 8) * 20 + q + 4 + s8];
            }
#pragma unroll
            for (int nt = 0; nt < 8; nt++) {
                int n = wn * 64 + nt * 8 + g;
                b[nt][0] = sb[n * 20 + q + s8];
                b[nt][1] = sb[n * 20 + q + 4 + s8];
            }
#pragma unroll
            for (int mt = 0; mt < 4; mt++)
#pragma unroll
                for (int nt = 0; nt < 8; nt++)
                    mma_bf16(acc[mt][nt], a[mt], b[nt]);
        }
        __syncthreads();
    }

    // epilogue: raw approx scores (bias added in pass 2)
#pragma unroll
    for (int mt = 0; mt < 4; mt++) {
        int r = row0 + wm * 64 + mt * 16 + g;
#pragma unroll
        for (int nt = 0; nt < 8; nt++) {
            int c = col0 + wn * 64 + nt * 8 + q * 2;
            float2 v0 = make_float2(acc[mt][nt][0], acc[mt][nt][1]);
            float2 v1 = make_float2(acc[mt][nt][2], acc[mt][nt][3]);
            *reinterpret_cast<float2*>(&g_scores[(size_t)r * K_CODES + c]) = v0;
            *reinterpret_cast<float2*>(&g_scores[(size_t)(r + 8) * K_CODES + c]) = v1;
        }
    }
}

// ---------------------------------------------------------------------------
// Pass 2: per-row max scan + margin candidates + exact fp32 rescore.
// ---------------------------------------------------------------------------
#define MAXCAND 64

__global__ __launch_bounds__(256) void select_kernel(const float* __restrict__ x,
                                                     const float* __restrict__ embed) {
    __shared__ __align__(16) float xs[DDIM];
    __shared__ float red[8];
    __shared__ float bcast;
    __shared__ int   cands[MAXCAND];
    __shared__ float cvals[MAXCAND];
    __shared__ int   cnt;
    __shared__ float rv[256];
    __shared__ int   ri[256];

    const int row = blockIdx.x;
    const int tid = threadIdx.x;
    const int lane = tid & 31;
    const int wid = tid >> 5;

    for (int i = tid; i < DDIM; i += 256) xs[i] = x[(size_t)row * DDIM + i];
    if (tid == 0) cnt = 0;

    const float4* s4 = reinterpret_cast<const float4*>(g_scores + (size_t)row * K_CODES);
    const float4* b4 = reinterpret_cast<const float4*>(g_bias);

    float m = -CUDART_INF_F;
    for (int i = tid; i < K_CODES / 4; i += 256) {
        float4 v = s4[i], b = b4[i];
        m = fmaxf(m, fmaxf(fmaxf(v.x + b.x, v.y + b.y), fmaxf(v.z + b.z, v.w + b.w)));
    }
#pragma unroll
    for (int off = 16; off; off >>= 1) m = fmaxf(m, __shfl_xor_sync(0xFFFFFFFFu, m, off));
    if (lane == 0) red[wid] = m;
    __syncthreads();
    if (tid == 0) {
        float mm = red[0];
#pragma unroll
        for (int i = 1; i < 8; i++) mm = fmaxf(mm, red[i]);
        bcast = mm;
    }
    __syncthreads();

    const float margin = 0.02f * g_xnorm[row] * sqrtf(__int_as_float(g_emax2)) + 0.5f;
    const float thr = bcast - margin;

    for (int i = tid; i < K_CODES / 4; i += 256) {
        float4 v = s4[i], b = b4[i];
        float val[4] = {v.x + b.x, v.y + b.y, v.z + b.z, v.w + b.w};
#pragma unroll
        for (int c = 0; c < 4; c++) {
            if (val[c] >= thr) {
                int p = atomicAdd(&cnt, 1);
                if (p < MAXCAND) cands[p] = i * 4 + c;
            }
        }
    }
    __syncthreads();
    const int n = cnt;

    if (n <= MAXCAND) {
        const float4* xs4 = reinterpret_cast<const float4*>(xs);
        for (int ci = wid; ci < n; ci += 8) {
            int k = cands[ci];
            const float4* e4 = reinterpret_cast<const float4*>(embed + (size_t)k * DDIM);
            float s = 0.f;
#pragma unroll
            for (int j = 0; j < 4; j++) {
                float4 ev = e4[lane + 32 * j];
                float4 xv = xs4[lane + 32 * j];
                s += xv.x * ev.x + xv.y * ev.y + xv.z * ev.z + xv.w * ev.w;
            }
#pragma unroll
            for (int off = 16; off; off >>= 1) s += __shfl_xor_sync(0xFFFFFFFFu, s, off);
            if (lane == 0) cvals[ci] = s + g_bias[k];
        }
        __syncthreads();
        if (tid == 0) {
            float best = -CUDART_INF_F;
            int bi = K_CODES;
            for (int ci = 0; ci < n; ci++) {
                float v = cvals[ci];
                int k = cands[ci];
                if (v > best || (v == best && k < bi)) { best = v; bi = k; }
            }
            g_ind[row] = bi;
        }
    } else {
        // overflow fallback: full exact scan (rare)
        const float4* xs4 = reinterpret_cast<const float4*>(xs);
        float best = -CUDART_INF_F;
        int bi = K_CODES;
        for (int k = tid; k < K_CODES; k += 256) {
            const float4* e4 = reinterpret_cast<const float4*>(embed + (size_t)k * DDIM);
            float s = 0.f;
            for (int j = 0; j < DDIM / 4; j++) {
                float4 ev = e4[j];
                float4 xv = xs4[j];
                s += xv.x * ev.x + xv.y * ev.y + xv.z * ev.z + xv.w * ev.w;
            }
            float v = s + g_bias[k];
            if (v > best || (v == best && k < bi)) { best = v; bi = k; }
        }
        rv[tid] = best; ri[tid] = bi;
        __syncthreads();
        if (tid == 0) {
            for (int t = 1; t < 256; t++) {
                if (rv[t] > best || (rv[t] == best && ri[t] < bi)) { best = rv[t]; bi = ri[t]; }
            }
            g_ind[row] = bi;
        }
    }
}

// ---------------------------------------------------------------------------
__global__ void gather_kernel(const float* __restrict__ embed,
                              float* __restrict__ out, int write_ind) {
    int nrow = blockIdx.x;
    int idx = g_ind[nrow];
    const float4* src = reinterpret_cast<const float4*>(embed + (size_t)idx * DDIM);
    float4*       dst = reinterpret_cast<float4*>(out + (size_t)nrow * DDIM);
    for (int i = threadIdx.x; i < DDIM / 4; i += blockDim.x) dst[i] = src[i];
    if (write_ind && threadIdx.x == 0) out[(size_t)N_ROWS * DDIM + nrow] = (float)idx;
}

// ---------------------------------------------------------------------------
extern "C" void kernel_launch(void* const* d_in, const int* in_sizes, int n_in,
                              void* d_out, int out_size) {
    const float* x     = (const float*)d_in[0];
    const float* embed = (const float*)d_in[1];
    float* out = (float*)d_out;
    (void)in_sizes; (void)n_in;
    int write_ind = (out_size >= N_ROWS * DDIM + N_ROWS) ? 1 : 0;

    cudaFuncSetAttribute(gemm_kernel, cudaFuncAttributeMaxDynamicSharedMemorySize, SMEM_GEMM);

    conv_x_kernel<<<N_ROWS / 8, 256>>>(x);
    conv_e_kernel<<<K_CODES / 8, 256>>>(embed);
    gemm_kernel<<<dim3(K_CODES / BN, N_ROWS / BM), 256, SMEM_GEMM>>>();
    select_kernel<<<N_ROWS, 256>>>(x, embed);
    gather_kernel<<<N_ROWS, 128>>>(embed, out, write_ind);
}